// round 12
// baseline (speedup 1.0000x reference)
#include <cuda_runtime.h>
#include <cuda_bf16.h>
#include <mma.h>
#include <math.h>

using namespace nvcuda;

// Problem constants
#define Nn   131072
#define Ee   1048576
#define Bb   1024
#define FIN  128
#define HID  128
#define DD   384
#define KK   30
#define C1n  16
#define C2n  32
#define KERNL 5
#define L2n  26
#define PL   13
#define FLAT 416
#define EPSc 1e-5f
#define SMAX 2048
#define SCANB 512

// ---- WMMA GEMM geometry -----------------------------------------------------
#define GTILE 128                      // rows per block
#define TILE_B 32768                   // 128x128 bf16 bytes (one plane)
#define BPAD 136                       // bf16 leading dim (272 bytes)
#define PLANE 34816                    // 128 * 272
#define SA0 0
#define SA1 34816
#define SA2 69632
#define SB0 104448
#define SB1 139264
#define SB2 174080
#define SMTOT 208896

// ---------------- scratch ----------------------------------------------------
__device__ float g_dis[Nn];
__device__ int   g_cnt[Nn];
__device__ int   g_offs[Nn + 1];
__device__ int   g_cursor[Nn];
__device__ int   g_csr[Ee];
__device__ float g_Agg[(size_t)Nn * HID];
__device__ float g_Y[(size_t)Nn * HID];
__device__ float g_X[(size_t)Nn * DD];
__device__ int   g_bcnt[Bb];
__device__ int   g_starts[Bb];
__device__ int   g_bsum[SCANB];
__device__ int   g_bbase[SCANB];
__device__ unsigned char g_Wb[3 * 3 * TILE_B];  // [layer][h/m/l] W^T bf16 row-major [n][k]

// ---------------- init -------------------------------------------------------
__global__ void init_kernel() {
    int i = blockIdx.x * blockDim.x + threadIdx.x;
    if (i < Nn) g_cnt[i] = 0;
    if (i < Bb) g_bcnt[i] = 0;
}

__global__ void count_kernel(const int* __restrict__ col, const int* __restrict__ batch) {
    int e = blockIdx.x * blockDim.x + threadIdx.x;
    if (e < Ee) atomicAdd(&g_cnt[col[e]], 1);
    if (e < Nn) atomicAdd(&g_bcnt[batch[e]], 1);
}

// ---------------- W^T 3-way bf16 split (row-major [n][k]) --------------------
__global__ void wtrans_kernel(const float* __restrict__ W0, const float* __restrict__ W1,
                              const float* __restrict__ W2) {
    int gid = blockIdx.x * 128 + threadIdx.x;    // 192*128 = 24576 = 3*8192
    int layer = gid >> 13;
    int e = gid & 8191;
    if (layer > 2) return;
    const float* W = (layer == 0) ? W0 : (layer == 1 ? W1 : W2);
    int n = e >> 6, kp = e & 63, k = 2 * kp;
    float a0 = W[k * 128 + n], a1 = W[(k + 1) * 128 + n];
    __nv_bfloat16 h0 = __float2bfloat16(a0), h1 = __float2bfloat16(a1);
    float r0 = a0 - __bfloat162float(h0), r1 = a1 - __bfloat162float(h1);
    __nv_bfloat16 m0 = __float2bfloat16(r0), m1 = __float2bfloat16(r1);
    float s0 = r0 - __bfloat162float(m0), s1 = r1 - __bfloat162float(m1);
    __nv_bfloat162 hv, mv, lv;
    hv.x = h0; hv.y = h1;
    mv.x = m0; mv.y = m1;
    lv.x = __float2bfloat16(s0); lv.y = __float2bfloat16(s1);
    size_t base = (size_t)layer * 3 * TILE_B;
    ((__nv_bfloat162*)(g_Wb + base))[n * 64 + kp] = hv;
    ((__nv_bfloat162*)(g_Wb + base + TILE_B))[n * 64 + kp] = mv;
    ((__nv_bfloat162*)(g_Wb + base + 2 * TILE_B))[n * 64 + kp] = lv;
}

// ---------------- hierarchical scan over node counts ------------------------
__global__ void scanA_kernel() {
    __shared__ int s[256];
    int tid = threadIdx.x;
    int i = blockIdx.x * 256 + tid;
    int c = g_cnt[i];
    s[tid] = c;
    __syncthreads();
    #pragma unroll
    for (int off = 1; off < 256; off <<= 1) {
        int v = (tid >= off) ? s[tid - off] : 0;
        __syncthreads();
        s[tid] += v;
        __syncthreads();
    }
    g_offs[i] = s[tid] - c;
    if (tid == 255) g_bsum[blockIdx.x] = s[255];
}

__global__ void scanB_kernel() {
    __shared__ int s[SCANB];
    int tid = threadIdx.x;
    int c = g_bsum[tid];
    s[tid] = c;
    __syncthreads();
    for (int off = 1; off < SCANB; off <<= 1) {
        int v = (tid >= off) ? s[tid - off] : 0;
        __syncthreads();
        s[tid] += v;
        __syncthreads();
    }
    g_bbase[tid] = s[tid] - c;
}

__global__ void scanC_kernel() {
    int tid = threadIdx.x;
    int i = blockIdx.x * 256 + tid;
    int o = g_offs[i] + g_bbase[blockIdx.x];
    g_offs[i] = o;
    g_cursor[i] = o;
    g_dis[i] = rsqrtf((float)(g_cnt[i] + 1));
    if (i == 0) g_offs[Nn] = Ee;
}

__global__ void scan_batch_kernel() {
    __shared__ int sbuf[Bb];
    int tid = threadIdx.x;
    int c = g_bcnt[tid];
    sbuf[tid] = c;
    __syncthreads();
    for (int off = 1; off < Bb; off <<= 1) {
        int v = (tid >= off) ? sbuf[tid - off] : 0;
        __syncthreads();
        sbuf[tid] += v;
        __syncthreads();
    }
    g_starts[tid] = sbuf[tid] - c;
}

__global__ void fill_kernel(const int* __restrict__ row, const int* __restrict__ col) {
    int e = blockIdx.x * blockDim.x + threadIdx.x;
    if (e >= Ee) return;
    int p = atomicAdd(&g_cursor[col[e]], 1);
    g_csr[p] = row[e];
}

// ---------------- layer-0 aggregation ---------------------------------------
__global__ void __launch_bounds__(256) agg0_kernel(const int* __restrict__ z) {
    __shared__ float bins[8][128];
    int w = threadIdx.x >> 5, lane = threadIdx.x & 31;
    int n = blockIdx.x * 8 + w;
    ((float4*)bins[w])[lane] = make_float4(0.f, 0.f, 0.f, 0.f);
    __syncwarp();
    int s = g_offs[n], e = g_offs[n + 1];
    for (int j = s + lane; j < e; j += 32) {
        int r = g_csr[j];
        atomicAdd(&bins[w][z[r]], g_dis[r]);
    }
    __syncwarp();
    if (lane == 0) bins[w][z[n]] += g_dis[n];
    __syncwarp();
    float dc = g_dis[n];
    float4 b = ((float4*)bins[w])[lane];
    b.x *= dc; b.y *= dc; b.z *= dc; b.w *= dc;
    ((float4*)(g_Agg + (size_t)n * HID))[lane] = b;
}

// ---------------- layers 1/2: CSR gather ------------------------------------
__global__ void __launch_bounds__(256) gather_kernel() {
    int gt = blockIdx.x * blockDim.x + threadIdx.x;
    int n = gt >> 5, lane = gt & 31;
    const float4* Y4 = (const float4*)g_Y;
    float4 acc = Y4[(size_t)n * 32 + lane];
    float4 acc2 = make_float4(0.f, 0.f, 0.f, 0.f);
    int s = g_offs[n], e = g_offs[n + 1];
    int j = s;
    for (; j + 2 <= e; j += 2) {
        int r0 = g_csr[j], r1 = g_csr[j + 1];
        float4 v0 = Y4[(size_t)r0 * 32 + lane];
        float4 v1 = Y4[(size_t)r1 * 32 + lane];
        acc.x += v0.x; acc.y += v0.y; acc.z += v0.z; acc.w += v0.w;
        acc2.x += v1.x; acc2.y += v1.y; acc2.z += v1.z; acc2.w += v1.w;
    }
    if (j < e) {
        int r = g_csr[j];
        float4 v = Y4[(size_t)r * 32 + lane];
        acc.x += v.x; acc.y += v.y; acc.z += v.z; acc.w += v.w;
    }
    acc.x += acc2.x; acc.y += acc2.y; acc.z += acc2.z; acc.w += acc2.w;
    float dc = g_dis[n];
    acc.x *= dc; acc.y *= dc; acc.z *= dc; acc.w *= dc;
    ((float4*)(g_Agg))[(size_t)n * 32 + lane] = acc;
}

// ---------------- WMMA GEMM: bf16 3-way split, 6 terms, tanh epilogue --------
// Block: 128 rows x 128 cols, 256 threads (8 warps x 16 rows x 8 n-tiles).
// D = Ah*Bh + Ah*Bm + Am*Bh + Ah*Bl + Am*Bm + Al*Bh   (fp32 accum)
__global__ void __launch_bounds__(256) gemm_wmma_kernel(const float* __restrict__ bias,
                                                        int layer, int out_off, int writeY) {
    extern __shared__ char sm[];
    int t = threadIdx.x, w = t >> 5;
    int rbase = blockIdx.x * GTILE;

    // stage B planes (row-major [n][k] -> padded stride 136)
    {
        const float4* src = (const float4*)(g_Wb + (size_t)layer * 3 * TILE_B);
        #pragma unroll
        for (int i = t; i < 6144; i += 256) {
            int plane = i >> 11, rem = i & 2047;
            int r = rem >> 4, c = rem & 15;
            *(float4*)(sm + SB0 + plane * PLANE + r * 272 + c * 16) = src[i];
        }
    }
    // stage A planes (fp32 -> 3-way split bf16, padded stride 136)
    {
        const float* A = g_Agg + (size_t)rbase * HID;
        #pragma unroll 4
        for (int i = 0; i < 32; ++i) {
            int e = t + i * 256;
            int r = e >> 6, cp = e & 63;
            float2 a = *(const float2*)(A + r * HID + 2 * cp);
            __nv_bfloat16 h0 = __float2bfloat16(a.x), h1 = __float2bfloat16(a.y);
            float r0 = a.x - __bfloat162float(h0), r1 = a.y - __bfloat162float(h1);
            __nv_bfloat16 m0 = __float2bfloat16(r0), m1 = __float2bfloat16(r1);
            float s0 = r0 - __bfloat162float(m0), s1 = r1 - __bfloat162float(m1);
            __nv_bfloat162 hv, mv, lv;
            hv.x = h0; hv.y = h1;
            mv.x = m0; mv.y = m1;
            lv.x = __float2bfloat16(s0); lv.y = __float2bfloat16(s1);
            int off = r * 272 + 4 * cp;
            *(__nv_bfloat162*)(sm + SA0 + off) = hv;
            *(__nv_bfloat162*)(sm + SA1 + off) = mv;
            *(__nv_bfloat162*)(sm + SA2 + off) = lv;
        }
    }
    __syncthreads();

    wmma::fragment<wmma::accumulator, 16, 16, 16, float> acc[8];
    #pragma unroll
    for (int n = 0; n < 8; ++n) wmma::fill_fragment(acc[n], 0.f);
    int row0 = w * 16;
    #pragma unroll
    for (int ks = 0; ks < 8; ++ks) {
        int k0 = ks * 16;
        wmma::fragment<wmma::matrix_a, 16, 16, 16, __nv_bfloat16, wmma::row_major> ah, am, al;
        wmma::load_matrix_sync(ah, (__nv_bfloat16*)(sm + SA0) + row0 * BPAD + k0, BPAD);
        wmma::load_matrix_sync(am, (__nv_bfloat16*)(sm + SA1) + row0 * BPAD + k0, BPAD);
        wmma::load_matrix_sync(al, (__nv_bfloat16*)(sm + SA2) + row0 * BPAD + k0, BPAD);
        #pragma unroll
        for (int n = 0; n < 8; ++n) {
            wmma::fragment<wmma::matrix_b, 16, 16, 16, __nv_bfloat16, wmma::col_major> bh, bm, bl;
            wmma::load_matrix_sync(bh, (__nv_bfloat16*)(sm + SB0) + n * 16 * BPAD + k0, BPAD);
            wmma::load_matrix_sync(bm, (__nv_bfloat16*)(sm + SB1) + n * 16 * BPAD + k0, BPAD);
            wmma::load_matrix_sync(bl, (__nv_bfloat16*)(sm + SB2) + n * 16 * BPAD + k0, BPAD);
            wmma::mma_sync(acc[n], ah, bh, acc[n]);
            wmma::mma_sync(acc[n], ah, bm, acc[n]);
            wmma::mma_sync(acc[n], am, bh, acc[n]);
            wmma::mma_sync(acc[n], ah, bl, acc[n]);
            wmma::mma_sync(acc[n], am, bm, acc[n]);
            wmma::mma_sync(acc[n], al, bh, acc[n]);
        }
    }
    __syncthreads();                                  // done reading A/B smem

    float* Sg = (float*)(sm + SA0);                   // [128][132] fp32 = 67584B
    #pragma unroll
    for (int n = 0; n < 8; ++n)
        wmma::store_matrix_sync(Sg + row0 * 132 + n * 16, acc[n], 132, wmma::mem_row_major);
    __syncthreads();

    #pragma unroll 4
    for (int i = 0; i < 16; ++i) {
        int e = t + i * 256;
        int r = e >> 5, c4 = e & 31;
        int rown = rbase + r;
        float4 v = *(float4*)(Sg + r * 132 + c4 * 4);
        v.x = tanhf(v.x + __ldg(&bias[c4 * 4 + 0]));
        v.y = tanhf(v.y + __ldg(&bias[c4 * 4 + 1]));
        v.z = tanhf(v.z + __ldg(&bias[c4 * 4 + 2]));
        v.w = tanhf(v.w + __ldg(&bias[c4 * 4 + 3]));
        *(float4*)(g_X + (size_t)rown * DD + out_off + c4 * 4) = v;
        if (writeY) {
            float dr = g_dis[rown];
            *(float4*)(g_Y + (size_t)rown * HID + c4 * 4) =
                make_float4(v.x * dr, v.y * dr, v.z * dr, v.w * dr);
        }
    }
}

// ---------------- per-graph head --------------------------------------------
__global__ void __launch_bounds__(256) head_kernel(
        const float* __restrict__ Wc1, const float* __restrict__ bc1,
        const float* __restrict__ Wc2, const float* __restrict__ bc2,
        const float* __restrict__ g1,  const float* __restrict__ be1,
        const float* __restrict__ g2,  const float* __restrict__ be2,
        const float* __restrict__ Wl1, const float* __restrict__ bl1,
        const float* __restrict__ Wl2, const float* __restrict__ bl2,
        const float* __restrict__ rm1, const float* __restrict__ rv1,
        const float* __restrict__ rm2, const float* __restrict__ rv2,
        float* __restrict__ out) {
    __shared__ float keys[SMAX];
    __shared__ int   topk[KK];
    __shared__ float Wc1s[C1n * DD];
    __shared__ float c1s[C1n * KK];
    __shared__ float h2s[C2n * L2n];
    __shared__ float ps[FLAT];
    __shared__ float f1[128];
    __shared__ float red[256];

    int b = blockIdx.x, tid = threadIdx.x, bd = blockDim.x;
    int M = g_bcnt[b];
    if (M > SMAX) M = SMAX;
    int s = g_starts[b];

    for (int i = tid; i < C1n * DD; i += bd) Wc1s[i] = Wc1[i];
    for (int i = tid; i < M; i += bd) keys[i] = g_X[(size_t)(s + i) * DD + (DD - 1)];
    for (int i = tid; i < KK; i += bd) topk[i] = -1;
    __syncthreads();

    for (int i = tid; i < M; i += bd) {
        float ki = keys[i];
        int r = 0;
        for (int j = 0; j < M; ++j) {
            float kj = keys[j];
            r += (kj > ki) || (kj == ki && j < i);
        }
        if (r < KK) topk[r] = s + i;
    }
    __syncthreads();

    for (int o = tid; o < C1n * KK; o += bd) {
        int c = o & 15, k = o >> 4;
        int node = topk[k];
        float acc = __ldg(&bc1[c]);
        if (node >= 0) {
            const float* xr = g_X + (size_t)node * DD;
            const float* w = Wc1s + c * DD;
            #pragma unroll 4
            for (int d = 0; d < DD; ++d) acc += xr[d] * w[d];
        }
        float v = fmaxf(acc, 0.f);
        v = (v - __ldg(&rm1[c])) * (__ldg(&g1[c]) * rsqrtf(__ldg(&rv1[c]) + EPSc)) + __ldg(&be1[c]);
        c1s[c * KK + k] = v;
    }
    __syncthreads();

    for (int o = tid; o < C2n * L2n; o += bd) {
        int oc = o / L2n, tt = o % L2n;
        float acc = __ldg(&bc2[oc]);
        const float* w = Wc2 + oc * (C1n * KERNL);
        for (int ic = 0; ic < C1n; ++ic) {
            #pragma unroll
            for (int kk = 0; kk < KERNL; ++kk)
                acc += c1s[ic * KK + tt + kk] * __ldg(&w[ic * KERNL + kk]);
        }
        float v = fmaxf(acc, 0.f);
        v = (v - __ldg(&rm2[oc])) * (__ldg(&g2[oc]) * rsqrtf(__ldg(&rv2[oc]) + EPSc)) + __ldg(&be2[oc]);
        h2s[oc * L2n + tt] = v;
    }
    __syncthreads();

    for (int o = tid; o < FLAT; o += bd) {
        int oc = o / PL, l = o % PL;
        ps[o] = fmaxf(h2s[oc * L2n + 2 * l], h2s[oc * L2n + 2 * l + 1]);
    }
    __syncthreads();

    for (int j = tid; j < 128; j += bd) {
        float acc = __ldg(&bl1[j]);
        const float* w = Wl1 + j * FLAT;
        #pragma unroll 4
        for (int i = 0; i < FLAT; ++i) acc += ps[i] * __ldg(&w[i]);
        f1[j] = fmaxf(acc, 0.f);
    }
    __syncthreads();

    float p = 0.f;
    if (tid < 128) p = f1[tid] * __ldg(&Wl2[tid]);
    red[tid] = p;
    __syncthreads();
    for (int off = 128; off > 0; off >>= 1) {
        if (tid < off && tid + off < bd) red[tid] += red[tid + off];
        __syncthreads();
    }
    if (tid == 0) out[b] = red[0] + __ldg(&bl2[0]);
}

// ---------------- host orchestration ----------------------------------------
extern "C" void kernel_launch(void* const* d_in, const int* in_sizes, int n_in,
                              void* d_out, int out_size) {
    const int*   z     = (const int*)d_in[0];
    const int*   ei    = (const int*)d_in[1];
    const int*   batch = (const int*)d_in[2];
    const float* W0    = (const float*)d_in[3];
    const float* b0    = (const float*)d_in[4];
    const float* W1    = (const float*)d_in[5];
    const float* b1    = (const float*)d_in[6];
    const float* W2    = (const float*)d_in[7];
    const float* b2    = (const float*)d_in[8];
    const float* Wc1   = (const float*)d_in[9];
    const float* bc1   = (const float*)d_in[10];
    const float* Wc2   = (const float*)d_in[11];
    const float* bc2   = (const float*)d_in[12];
    const float* g1    = (const float*)d_in[13];
    const float* be1   = (const float*)d_in[14];
    const float* g2    = (const float*)d_in[15];
    const float* be2   = (const float*)d_in[16];
    const float* Wl1   = (const float*)d_in[17];
    const float* bl1   = (const float*)d_in[18];
    const float* Wl2   = (const float*)d_in[19];
    const float* bl2   = (const float*)d_in[20];
    const float* rm1   = (const float*)d_in[21];
    const float* rv1   = (const float*)d_in[22];
    const float* rm2   = (const float*)d_in[23];
    const float* rv2   = (const float*)d_in[24];
    float* out = (float*)d_out;

    const int* row = ei;
    const int* col = ei + Ee;

    cudaFuncSetAttribute(gemm_wmma_kernel,
                         cudaFuncAttributeMaxDynamicSharedMemorySize, SMTOT);

    init_kernel<<<(Nn + 255) / 256, 256>>>();                          // 0
    count_kernel<<<(Ee + 255) / 256, 256>>>(col, batch);               // 1
    wtrans_kernel<<<192, 128>>>(W0, W1, W2);                           // 2
    // PROBE (profiled slot): quarter-size WMMA GEMM; outputs overwritten.
    gemm_wmma_kernel<<<256, 256, SMTOT>>>(b0, 0, 0, 1);                // 3  <-- profiled
    scanA_kernel<<<SCANB, 256>>>();                                    // 4
    scanB_kernel<<<1, SCANB>>>();                                      // 5
    scanC_kernel<<<SCANB, 256>>>();                                    // 6
    scan_batch_kernel<<<1, Bb>>>();                                    // 7
    fill_kernel<<<(Ee + 255) / 256, 256>>>(row, col);                  // 8

    agg0_kernel<<<Nn / 8, 256>>>(z);                                   // 9
    gemm_wmma_kernel<<<Nn / GTILE, 256, SMTOT>>>(b0, 0, 0, 1);         // 10

    gather_kernel<<<Nn * 32 / 256, 256>>>();                           // 11
    gemm_wmma_kernel<<<Nn / GTILE, 256, SMTOT>>>(b1, 1, HID, 1);       // 12

    gather_kernel<<<Nn * 32 / 256, 256>>>();                           // 13
    gemm_wmma_kernel<<<Nn / GTILE, 256, SMTOT>>>(b2, 2, 2 * HID, 0);   // 14

    head_kernel<<<Bb, 256>>>(Wc1, bc1, Wc2, bc2, g1, be1, g2, be2,
                             Wl1, bl1, Wl2, bl2, rm1, rv1, rm2, rv2, out);  // 15
}

// round 13
// speedup vs baseline: 1.1483x; 1.1483x over previous
#include <cuda_runtime.h>
#include <math.h>

// Problem constants
#define Nn   131072
#define Ee   1048576
#define Bb   1024
#define FIN  128
#define HID  128
#define DD   384
#define KK   30
#define C1n  16
#define C2n  32
#define KERNL 5
#define L2n  26
#define PL   13
#define FLAT 416
#define EPSc 1e-5f
#define SMAX 2048
#define SCANB 512

// packed fp32x2 helpers
#define PACKF2(out, lo, hi) \
    asm("mov.b64 %0, {%1, %2};" : "=l"(out) : "r"(__float_as_uint(lo)), "r"(__float_as_uint(hi)))
#define UNPACKF2(lo, hi, in) \
    { unsigned int _a, _b; asm("mov.b64 {%0, %1}, %2;" : "=r"(_a), "=r"(_b) : "l"(in)); \
      lo = __uint_as_float(_a); hi = __uint_as_float(_b); }
#define FMAF2(acc, a, b) \
    asm("fma.rn.f32x2 %0, %1, %2, %0;" : "+l"(acc) : "l"(a), "l"(b))

// ---------------- scratch ----------------------------------------------------
__device__ float g_dis[Nn];
__device__ int   g_cnt[Nn];
__device__ int   g_offs[Nn + 1];
__device__ int   g_cursor[Nn];
__device__ int   g_csr[Ee];
__device__ float g_Agg[(size_t)Nn * HID];
__device__ float g_Y[(size_t)Nn * HID];
__device__ float g_X[(size_t)Nn * DD];
__device__ int   g_bcnt[Bb];
__device__ int   g_starts[Bb];
__device__ int   g_bsum[SCANB];
__device__ int   g_bbase[SCANB];

// ---------------- init -------------------------------------------------------
__global__ void init_kernel() {
    int i = blockIdx.x * blockDim.x + threadIdx.x;
    if (i < Nn) g_cnt[i] = 0;
    if (i < Bb) g_bcnt[i] = 0;
}

__global__ void count_kernel(const int* __restrict__ col, const int* __restrict__ batch) {
    int e = blockIdx.x * blockDim.x + threadIdx.x;
    if (e < Ee) atomicAdd(&g_cnt[col[e]], 1);
    if (e < Nn) atomicAdd(&g_bcnt[batch[e]], 1);
}

// ---------------- hierarchical scan over node counts ------------------------
__global__ void scanA_kernel() {
    __shared__ int s[256];
    int tid = threadIdx.x;
    int i = blockIdx.x * 256 + tid;
    int c = g_cnt[i];
    s[tid] = c;
    __syncthreads();
    #pragma unroll
    for (int off = 1; off < 256; off <<= 1) {
        int v = (tid >= off) ? s[tid - off] : 0;
        __syncthreads();
        s[tid] += v;
        __syncthreads();
    }
    g_offs[i] = s[tid] - c;
    if (tid == 255) g_bsum[blockIdx.x] = s[255];
}

__global__ void scanB_kernel() {
    __shared__ int s[SCANB];
    int tid = threadIdx.x;
    int c = g_bsum[tid];
    s[tid] = c;
    __syncthreads();
    for (int off = 1; off < SCANB; off <<= 1) {
        int v = (tid >= off) ? s[tid - off] : 0;
        __syncthreads();
        s[tid] += v;
        __syncthreads();
    }
    g_bbase[tid] = s[tid] - c;
}

__global__ void scanC_kernel() {
    int tid = threadIdx.x;
    int i = blockIdx.x * 256 + tid;
    int o = g_offs[i] + g_bbase[blockIdx.x];
    g_offs[i] = o;
    g_cursor[i] = o;
    g_dis[i] = rsqrtf((float)(g_cnt[i] + 1));
    if (i == 0) g_offs[Nn] = Ee;
}

__global__ void scan_batch_kernel() {
    __shared__ int sbuf[Bb];
    int tid = threadIdx.x;
    int c = g_bcnt[tid];
    sbuf[tid] = c;
    __syncthreads();
    for (int off = 1; off < Bb; off <<= 1) {
        int v = (tid >= off) ? sbuf[tid - off] : 0;
        __syncthreads();
        sbuf[tid] += v;
        __syncthreads();
    }
    g_starts[tid] = sbuf[tid] - c;
}

__global__ void fill_kernel(const int* __restrict__ row, const int* __restrict__ col) {
    int e = blockIdx.x * blockDim.x + threadIdx.x;
    if (e >= Ee) return;
    int p = atomicAdd(&g_cursor[col[e]], 1);
    g_csr[p] = row[e];
}

// ---------------- synthetic agg0 PROBE (profiling only) ----------------------
// Same pattern as agg0: per-warp smem histogram, random z reads, 8 hash
// neighbors per node. Output region fully overwritten by the real agg0 later.
__global__ void __launch_bounds__(256) agg0_probe_kernel(const int* __restrict__ z) {
    __shared__ float bins[8][128];
    int w = threadIdx.x >> 5, lane = threadIdx.x & 31;
    int n = blockIdx.x * 8 + w;
    ((float4*)bins[w])[lane] = make_float4(0.f, 0.f, 0.f, 0.f);
    __syncwarp();
    unsigned int h = ((unsigned int)n * 2654435761u) ^ (lane * 0x9E3779B9u);
    #pragma unroll
    for (int j = 0; j < 8; ++j) {
        int r = (h >> 7) & (Nn - 1);
        h = h * 1664525u + 1013904223u;
        atomicAdd(&bins[w][z[r]], g_dis[r]);
    }
    __syncwarp();
    float4 b = ((float4*)bins[w])[lane];
    ((float4*)(g_Agg + (size_t)n * HID))[lane] = b;
}

// ---------------- layer-0 aggregation ---------------------------------------
__global__ void __launch_bounds__(256) agg0_kernel(const int* __restrict__ z) {
    __shared__ float bins[8][128];
    int w = threadIdx.x >> 5, lane = threadIdx.x & 31;
    int n = blockIdx.x * 8 + w;
    ((float4*)bins[w])[lane] = make_float4(0.f, 0.f, 0.f, 0.f);
    __syncwarp();
    int s = g_offs[n], e = g_offs[n + 1];
    for (int j = s + lane; j < e; j += 32) {
        int r = g_csr[j];
        atomicAdd(&bins[w][z[r]], g_dis[r]);
    }
    __syncwarp();
    if (lane == 0) bins[w][z[n]] += g_dis[n];
    __syncwarp();
    float dc = g_dis[n];
    float4 b = ((float4*)bins[w])[lane];
    b.x *= dc; b.y *= dc; b.z *= dc; b.w *= dc;
    ((float4*)(g_Agg + (size_t)n * HID))[lane] = b;
}

// ---------------- layers 1/2: CSR gather (unroll x4) -------------------------
__global__ void __launch_bounds__(256) gather_kernel() {
    int gt = blockIdx.x * blockDim.x + threadIdx.x;
    int n = gt >> 5, lane = gt & 31;
    const float4* Y4 = (const float4*)g_Y;
    float4 acc = Y4[(size_t)n * 32 + lane];
    float4 acc2 = make_float4(0.f, 0.f, 0.f, 0.f);
    int s = g_offs[n], e = g_offs[n + 1];
    int j = s;
    for (; j + 4 <= e; j += 4) {
        int r0 = g_csr[j], r1 = g_csr[j + 1], r2 = g_csr[j + 2], r3 = g_csr[j + 3];
        float4 v0 = Y4[(size_t)r0 * 32 + lane];
        float4 v1 = Y4[(size_t)r1 * 32 + lane];
        float4 v2 = Y4[(size_t)r2 * 32 + lane];
        float4 v3 = Y4[(size_t)r3 * 32 + lane];
        acc.x += v0.x + v2.x; acc.y += v0.y + v2.y;
        acc.z += v0.z + v2.z; acc.w += v0.w + v2.w;
        acc2.x += v1.x + v3.x; acc2.y += v1.y + v3.y;
        acc2.z += v1.z + v3.z; acc2.w += v1.w + v3.w;
    }
    for (; j < e; ++j) {
        int r = g_csr[j];
        float4 v = Y4[(size_t)r * 32 + lane];
        acc.x += v.x; acc.y += v.y; acc.z += v.z; acc.w += v.w;
    }
    acc.x += acc2.x; acc.y += acc2.y; acc.z += acc2.z; acc.w += acc2.w;
    float dc = g_dis[n];
    acc.x *= dc; acc.y *= dc; acc.z *= dc; acc.w *= dc;
    ((float4*)(g_Agg))[(size_t)n * 32 + lane] = acc;
}

// ---------------- GEMM v5: 64x128 tile, 128 thr, 8x8, conflict-free W -------
#define AROWS 132
__global__ void __launch_bounds__(128, 4) gemm_tanh_kernel(const float* __restrict__ W,
                                                           const float* __restrict__ bias,
                                                           int out_off, int writeY) {
    __shared__ float As[64 * AROWS];
    __shared__ unsigned long long Wp[16 * 4 * 16];   // [kk][p][tx]
    int t = threadIdx.x;
    int rbase = blockIdx.x * 64;
    int tx = t & 15, ty = t >> 4;
    int row0 = ty * 8;

    {
        const float4* A4 = (const float4*)(g_Agg + (size_t)rbase * HID);
        #pragma unroll
        for (int i = 0; i < 16; ++i) {
            int idx = t + i * 128;
            int r = idx >> 5, c4 = idx & 31;
            *(float4*)(As + r * AROWS + c4 * 4) = A4[idx];
        }
    }

    unsigned long long acc[8][4];
    #pragma unroll
    for (int i = 0; i < 8; ++i)
        #pragma unroll
        for (int p = 0; p < 4; ++p) acc[i][p] = 0ull;

    for (int kc = 0; kc < 8; ++kc) {
        __syncthreads();
        {
            const float* Wk = W + kc * 16 * 128;
            #pragma unroll
            for (int i = 0; i < 8; ++i) {
                int idx = t + i * 128;
                int kk = idx >> 6, rem = idx & 63;
                int p = rem >> 4, txc = rem & 15;
                float lo = Wk[kk * 128 + 32 * p + txc];
                float hi = Wk[kk * 128 + 32 * p + txc + 16];
                unsigned long long pr;
                PACKF2(pr, lo, hi);
                Wp[idx] = pr;
            }
        }
        __syncthreads();
        #pragma unroll
        for (int kk = 0; kk < 16; ++kk) {
            int k = kc * 16 + kk;
            unsigned long long ad[8];
            #pragma unroll
            for (int i = 0; i < 8; ++i) {
                float a = As[(row0 + i) * AROWS + k];
                PACKF2(ad[i], a, a);
            }
            unsigned long long w0 = Wp[(kk * 4 + 0) * 16 + tx];
            unsigned long long w1 = Wp[(kk * 4 + 1) * 16 + tx];
            unsigned long long w2 = Wp[(kk * 4 + 2) * 16 + tx];
            unsigned long long w3 = Wp[(kk * 4 + 3) * 16 + tx];
            #pragma unroll
            for (int i = 0; i < 8; ++i) {
                FMAF2(acc[i][0], ad[i], w0);
                FMAF2(acc[i][1], ad[i], w1);
                FMAF2(acc[i][2], ad[i], w2);
                FMAF2(acc[i][3], ad[i], w3);
            }
        }
    }

    float blo[4], bhi[4];
    #pragma unroll
    for (int p = 0; p < 4; ++p) {
        blo[p] = __ldg(&bias[tx + 32 * p]);
        bhi[p] = __ldg(&bias[tx + 32 * p + 16]);
    }

    #pragma unroll
    for (int i = 0; i < 8; ++i) {
        int rown = rbase + row0 + i;
        float dr = g_dis[rown];
        float* o = g_X + (size_t)rown * DD + out_off;
        float* y = g_Y + (size_t)rown * HID;
        #pragma unroll
        for (int p = 0; p < 4; ++p) {
            float lo, hi;
            UNPACKF2(lo, hi, acc[i][p]);
            float vlo = tanhf(lo + blo[p]);
            float vhi = tanhf(hi + bhi[p]);
            int clo = tx + 32 * p, chi = clo + 16;
            o[clo] = vlo;
            o[chi] = vhi;
            if (writeY) { y[clo] = vlo * dr; y[chi] = vhi * dr; }
        }
    }
}

// ---------------- per-graph head --------------------------------------------
__global__ void __launch_bounds__(256) head_kernel(
        const float* __restrict__ Wc1, const float* __restrict__ bc1,
        const float* __restrict__ Wc2, const float* __restrict__ bc2,
        const float* __restrict__ g1,  const float* __restrict__ be1,
        const float* __restrict__ g2,  const float* __restrict__ be2,
        const float* __restrict__ Wl1, const float* __restrict__ bl1,
        const float* __restrict__ Wl2, const float* __restrict__ bl2,
        const float* __restrict__ rm1, const float* __restrict__ rv1,
        const float* __restrict__ rm2, const float* __restrict__ rv2,
        float* __restrict__ out) {
    __shared__ float keys[SMAX];
    __shared__ int   topk[KK];
    __shared__ float Wc1s[C1n * DD];
    __shared__ float c1s[C1n * KK];
    __shared__ float h2s[C2n * L2n];
    __shared__ float ps[FLAT];
    __shared__ float f1[128];
    __shared__ float red[256];

    int b = blockIdx.x, tid = threadIdx.x, bd = blockDim.x;
    int M = g_bcnt[b];
    if (M > SMAX) M = SMAX;
    int s = g_starts[b];

    for (int i = tid; i < C1n * DD; i += bd) Wc1s[i] = Wc1[i];
    for (int i = tid; i < M; i += bd) keys[i] = g_X[(size_t)(s + i) * DD + (DD - 1)];
    for (int i = tid; i < KK; i += bd) topk[i] = -1;
    __syncthreads();

    for (int i = tid; i < M; i += bd) {
        float ki = keys[i];
        int r = 0;
        for (int j = 0; j < M; ++j) {
            float kj = keys[j];
            r += (kj > ki) || (kj == ki && j < i);
        }
        if (r < KK) topk[r] = s + i;
    }
    __syncthreads();

    for (int o = tid; o < C1n * KK; o += bd) {
        int c = o & 15, k = o >> 4;
        int node = topk[k];
        float acc = __ldg(&bc1[c]);
        if (node >= 0) {
            const float* xr = g_X + (size_t)node * DD;
            const float* w = Wc1s + c * DD;
            #pragma unroll 4
            for (int d = 0; d < DD; ++d) acc += xr[d] * w[d];
        }
        float v = fmaxf(acc, 0.f);
        v = (v - __ldg(&rm1[c])) * (__ldg(&g1[c]) * rsqrtf(__ldg(&rv1[c]) + EPSc)) + __ldg(&be1[c]);
        c1s[c * KK + k] = v;
    }
    __syncthreads();

    for (int o = tid; o < C2n * L2n; o += bd) {
        int oc = o / L2n, tt = o % L2n;
        float acc = __ldg(&bc2[oc]);
        const float* w = Wc2 + oc * (C1n * KERNL);
        for (int ic = 0; ic < C1n; ++ic) {
            #pragma unroll
            for (int kk = 0; kk < KERNL; ++kk)
                acc += c1s[ic * KK + tt + kk] * __ldg(&w[ic * KERNL + kk]);
        }
        float v = fmaxf(acc, 0.f);
        v = (v - __ldg(&rm2[oc])) * (__ldg(&g2[oc]) * rsqrtf(__ldg(&rv2[oc]) + EPSc)) + __ldg(&be2[oc]);
        h2s[oc * L2n + tt] = v;
    }
    __syncthreads();

    for (int o = tid; o < FLAT; o += bd) {
        int oc = o / PL, l = o % PL;
        ps[o] = fmaxf(h2s[oc * L2n + 2 * l], h2s[oc * L2n + 2 * l + 1]);
    }
    __syncthreads();

    for (int j = tid; j < 128; j += bd) {
        float acc = __ldg(&bl1[j]);
        const float* w = Wl1 + j * FLAT;
        #pragma unroll 4
        for (int i = 0; i < FLAT; ++i) acc += ps[i] * __ldg(&w[i]);
        f1[j] = fmaxf(acc, 0.f);
    }
    __syncthreads();

    float p = 0.f;
    if (tid < 128) p = f1[tid] * __ldg(&Wl2[tid]);
    red[tid] = p;
    __syncthreads();
    for (int off = 128; off > 0; off >>= 1) {
        if (tid < off && tid + off < bd) red[tid] += red[tid + off];
        __syncthreads();
    }
    if (tid == 0) out[b] = red[0] + __ldg(&bl2[0]);
}

// ---------------- host orchestration ----------------------------------------
extern "C" void kernel_launch(void* const* d_in, const int* in_sizes, int n_in,
                              void* d_out, int out_size) {
    const int*   z     = (const int*)d_in[0];
    const int*   ei    = (const int*)d_in[1];
    const int*   batch = (const int*)d_in[2];
    const float* W0    = (const float*)d_in[3];
    const float* b0    = (const float*)d_in[4];
    const float* W1    = (const float*)d_in[5];
    const float* b1    = (const float*)d_in[6];
    const float* W2    = (const float*)d_in[7];
    const float* b2    = (const float*)d_in[8];
    const float* Wc1   = (const float*)d_in[9];
    const float* bc1   = (const float*)d_in[10];
    const float* Wc2   = (const float*)d_in[11];
    const float* bc2   = (const float*)d_in[12];
    const float* g1    = (const float*)d_in[13];
    const float* be1   = (const float*)d_in[14];
    const float* g2    = (const float*)d_in[15];
    const float* be2   = (const float*)d_in[16];
    const float* Wl1   = (const float*)d_in[17];
    const float* bl1   = (const float*)d_in[18];
    const float* Wl2   = (const float*)d_in[19];
    const float* bl2   = (const float*)d_in[20];
    const float* rm1   = (const float*)d_in[21];
    const float* rv1   = (const float*)d_in[22];
    const float* rm2   = (const float*)d_in[23];
    const float* rv2   = (const float*)d_in[24];
    float* out = (float*)d_out;

    const int* row = ei;
    const int* col = ei + Ee;

    init_kernel<<<(Nn + 255) / 256, 256>>>();                 // 0
    count_kernel<<<(Ee + 255) / 256, 256>>>(col, batch);      // 1
    scanA_kernel<<<SCANB, 256>>>();                           // 2
    // PROBE (profiled slot): quarter-scale synthetic agg0; output overwritten
    // by the real agg0 below.
    agg0_probe_kernel<<<4096, 256>>>(z);                      // 3  <-- profiled
    scanB_kernel<<<1, SCANB>>>();                             // 4
    scanC_kernel<<<SCANB, 256>>>();                           // 5
    scan_batch_kernel<<<1, Bb>>>();                           // 6
    fill_kernel<<<(Ee + 255) / 256, 256>>>(row, col);         // 7

    agg0_kernel<<<Nn / 8, 256>>>(z);                          // 8
    gemm_tanh_kernel<<<Nn / 64, 128>>>(W0, b0, 0, 1);         // 9

    gather_kernel<<<Nn * 32 / 256, 256>>>();                  // 10
    gemm_tanh_kernel<<<Nn / 64, 128>>>(W1, b1, HID, 1);       // 11

    gather_kernel<<<Nn * 32 / 256, 256>>>();                  // 12
    gemm_tanh_kernel<<<Nn / 64, 128>>>(W2, b2, 2 * HID, 0);   // 13

    head_kernel<<<Bb, 256>>>(Wc1, bc1, Wc2, bc2, g1, be1, g2, be2,
                             Wl1, bl1, Wl2, bl2, rm1, rv1, rm2, rv2, out);  // 14
}

// round 14
// speedup vs baseline: 1.2090x; 1.0529x over previous
#include <cuda_runtime.h>
#include <math.h>

// Problem constants
#define Nn   131072
#define Ee   1048576
#define Bb   1024
#define FIN  128
#define HID  128
#define DD   384
#define KK   30
#define C1n  16
#define C2n  32
#define KERNL 5
#define L2n  26
#define PL   13
#define FLAT 416
#define EPSc 1e-5f
#define SMAX 2048
#define SCANB 512

// packed fp32x2 helpers
#define PACKF2(out, lo, hi) \
    asm("mov.b64 %0, {%1, %2};" : "=l"(out) : "r"(__float_as_uint(lo)), "r"(__float_as_uint(hi)))
#define UNPACKF2(lo, hi, in) \
    { unsigned int _a, _b; asm("mov.b64 {%0, %1}, %2;" : "=r"(_a), "=r"(_b) : "l"(in)); \
      lo = __uint_as_float(_a); hi = __uint_as_float(_b); }
#define FMAF2(acc, a, b) \
    asm("fma.rn.f32x2 %0, %1, %2, %0;" : "+l"(acc) : "l"(a), "l"(b))

// ---------------- scratch ----------------------------------------------------
__device__ float g_dis[Nn];
__device__ int   g_cnt[Nn];
__device__ int   g_offs[Nn + 1];
__device__ int   g_cursor[Nn];
__device__ int   g_csr[Ee];
__device__ float g_Agg[(size_t)Nn * HID];
__device__ float g_Y[(size_t)Nn * HID];
__device__ float g_X[(size_t)Nn * DD];
__device__ int   g_bcnt[Bb];
__device__ int   g_starts[Bb];
__device__ int   g_bsum[SCANB];
__device__ int   g_bbase[SCANB];

// ---------------- init -------------------------------------------------------
__global__ void init_kernel() {
    int i = blockIdx.x * blockDim.x + threadIdx.x;
    if (i < Nn) g_cnt[i] = 0;
    if (i < Bb) g_bcnt[i] = 0;
}

__global__ void count_kernel(const int* __restrict__ col, const int* __restrict__ batch) {
    int e = blockIdx.x * blockDim.x + threadIdx.x;
    if (e < Ee) atomicAdd(&g_cnt[col[e]], 1);
    if (e < Nn) atomicAdd(&g_bcnt[batch[e]], 1);
}

// ---------------- hierarchical scan over node counts ------------------------
__global__ void scanA_kernel() {
    __shared__ int s[256];
    int tid = threadIdx.x;
    int i = blockIdx.x * 256 + tid;
    int c = g_cnt[i];
    s[tid] = c;
    __syncthreads();
    #pragma unroll
    for (int off = 1; off < 256; off <<= 1) {
        int v = (tid >= off) ? s[tid - off] : 0;
        __syncthreads();
        s[tid] += v;
        __syncthreads();
    }
    g_offs[i] = s[tid] - c;
    if (tid == 255) g_bsum[blockIdx.x] = s[255];
}

__global__ void scanB_kernel() {
    __shared__ int s[SCANB];
    int tid = threadIdx.x;
    int c = g_bsum[tid];
    s[tid] = c;
    __syncthreads();
    for (int off = 1; off < SCANB; off <<= 1) {
        int v = (tid >= off) ? s[tid - off] : 0;
        __syncthreads();
        s[tid] += v;
        __syncthreads();
    }
    g_bbase[tid] = s[tid] - c;
}

__global__ void scanC_kernel() {
    int tid = threadIdx.x;
    int i = blockIdx.x * 256 + tid;
    int o = g_offs[i] + g_bbase[blockIdx.x];
    g_offs[i] = o;
    g_cursor[i] = o;
    g_dis[i] = rsqrtf((float)(g_cnt[i] + 1));
    if (i == 0) g_offs[Nn] = Ee;
}

__global__ void scan_batch_kernel() {
    __shared__ int sbuf[Bb];
    int tid = threadIdx.x;
    int c = g_bcnt[tid];
    sbuf[tid] = c;
    __syncthreads();
    for (int off = 1; off < Bb; off <<= 1) {
        int v = (tid >= off) ? sbuf[tid - off] : 0;
        __syncthreads();
        sbuf[tid] += v;
        __syncthreads();
    }
    g_starts[tid] = sbuf[tid] - c;
}

__global__ void fill_kernel(const int* __restrict__ row, const int* __restrict__ col) {
    int e = blockIdx.x * blockDim.x + threadIdx.x;
    if (e >= Ee) return;
    int p = atomicAdd(&g_cursor[col[e]], 1);
    g_csr[p] = row[e];
}

// ---------------- layer-0 aggregation ---------------------------------------
__global__ void __launch_bounds__(256) agg0_kernel(const int* __restrict__ z) {
    __shared__ float bins[8][128];
    int w = threadIdx.x >> 5, lane = threadIdx.x & 31;
    int n = blockIdx.x * 8 + w;
    ((float4*)bins[w])[lane] = make_float4(0.f, 0.f, 0.f, 0.f);
    __syncwarp();
    int s = g_offs[n], e = g_offs[n + 1];
    for (int j = s + lane; j < e; j += 32) {
        int r = g_csr[j];
        atomicAdd(&bins[w][z[r]], g_dis[r]);
    }
    __syncwarp();
    if (lane == 0) bins[w][z[n]] += g_dis[n];
    __syncwarp();
    float dc = g_dis[n];
    float4 b = ((float4*)bins[w])[lane];
    b.x *= dc; b.y *= dc; b.z *= dc; b.w *= dc;
    ((float4*)(g_Agg + (size_t)n * HID))[lane] = b;
}

// ---------------- layers 1/2: CSR gather (unroll x4) -------------------------
__global__ void __launch_bounds__(256) gather_kernel() {
    int gt = blockIdx.x * blockDim.x + threadIdx.x;
    int n = gt >> 5, lane = gt & 31;
    const float4* Y4 = (const float4*)g_Y;
    float4 acc = Y4[(size_t)n * 32 + lane];
    float4 acc2 = make_float4(0.f, 0.f, 0.f, 0.f);
    int s = g_offs[n], e = g_offs[n + 1];
    int j = s;
    for (; j + 4 <= e; j += 4) {
        int r0 = g_csr[j], r1 = g_csr[j + 1], r2 = g_csr[j + 2], r3 = g_csr[j + 3];
        float4 v0 = Y4[(size_t)r0 * 32 + lane];
        float4 v1 = Y4[(size_t)r1 * 32 + lane];
        float4 v2 = Y4[(size_t)r2 * 32 + lane];
        float4 v3 = Y4[(size_t)r3 * 32 + lane];
        acc.x += v0.x + v2.x; acc.y += v0.y + v2.y;
        acc.z += v0.z + v2.z; acc.w += v0.w + v2.w;
        acc2.x += v1.x + v3.x; acc2.y += v1.y + v3.y;
        acc2.z += v1.z + v3.z; acc2.w += v1.w + v3.w;
    }
    for (; j < e; ++j) {
        int r = g_csr[j];
        float4 v = Y4[(size_t)r * 32 + lane];
        acc.x += v.x; acc.y += v.y; acc.z += v.z; acc.w += v.w;
    }
    acc.x += acc2.x; acc.y += acc2.y; acc.z += acc2.z; acc.w += acc2.w;
    float dc = g_dis[n];
    acc.x *= dc; acc.y *= dc; acc.z *= dc; acc.w *= dc;
    ((float4*)(g_Agg))[(size_t)n * 32 + lane] = acc;
}

// ---------------- GEMM v5: 64x128 tile, 128 thr, 8x8, conflict-free W -------
#define AROWS 132
__global__ void __launch_bounds__(128, 4) gemm_tanh_kernel(const float* __restrict__ W,
                                                           const float* __restrict__ bias,
                                                           int out_off, int writeY) {
    __shared__ float As[64 * AROWS];
    __shared__ unsigned long long Wp[16 * 4 * 16];   // [kk][p][tx]
    int t = threadIdx.x;
    int rbase = blockIdx.x * 64;
    int tx = t & 15, ty = t >> 4;
    int row0 = ty * 8;

    {
        const float4* A4 = (const float4*)(g_Agg + (size_t)rbase * HID);
        #pragma unroll
        for (int i = 0; i < 16; ++i) {
            int idx = t + i * 128;
            int r = idx >> 5, c4 = idx & 31;
            *(float4*)(As + r * AROWS + c4 * 4) = A4[idx];
        }
    }

    unsigned long long acc[8][4];
    #pragma unroll
    for (int i = 0; i < 8; ++i)
        #pragma unroll
        for (int p = 0; p < 4; ++p) acc[i][p] = 0ull;

    for (int kc = 0; kc < 8; ++kc) {
        __syncthreads();
        {
            const float* Wk = W + kc * 16 * 128;
            #pragma unroll
            for (int i = 0; i < 8; ++i) {
                int idx = t + i * 128;
                int kk = idx >> 6, rem = idx & 63;
                int p = rem >> 4, txc = rem & 15;
                float lo = Wk[kk * 128 + 32 * p + txc];
                float hi = Wk[kk * 128 + 32 * p + txc + 16];
                unsigned long long pr;
                PACKF2(pr, lo, hi);
                Wp[idx] = pr;
            }
        }
        __syncthreads();
        #pragma unroll
        for (int kk = 0; kk < 16; ++kk) {
            int k = kc * 16 + kk;
            unsigned long long ad[8];
            #pragma unroll
            for (int i = 0; i < 8; ++i) {
                float a = As[(row0 + i) * AROWS + k];
                PACKF2(ad[i], a, a);
            }
            unsigned long long w0 = Wp[(kk * 4 + 0) * 16 + tx];
            unsigned long long w1 = Wp[(kk * 4 + 1) * 16 + tx];
            unsigned long long w2 = Wp[(kk * 4 + 2) * 16 + tx];
            unsigned long long w3 = Wp[(kk * 4 + 3) * 16 + tx];
            #pragma unroll
            for (int i = 0; i < 8; ++i) {
                FMAF2(acc[i][0], ad[i], w0);
                FMAF2(acc[i][1], ad[i], w1);
                FMAF2(acc[i][2], ad[i], w2);
                FMAF2(acc[i][3], ad[i], w3);
            }
        }
    }

    float blo[4], bhi[4];
    #pragma unroll
    for (int p = 0; p < 4; ++p) {
        blo[p] = __ldg(&bias[tx + 32 * p]);
        bhi[p] = __ldg(&bias[tx + 32 * p + 16]);
    }

    #pragma unroll
    for (int i = 0; i < 8; ++i) {
        int rown = rbase + row0 + i;
        float dr = g_dis[rown];
        float* o = g_X + (size_t)rown * DD + out_off;
        float* y = g_Y + (size_t)rown * HID;
        #pragma unroll
        for (int p = 0; p < 4; ++p) {
            float lo, hi;
            UNPACKF2(lo, hi, acc[i][p]);
            float vlo = tanhf(lo + blo[p]);
            float vhi = tanhf(hi + bhi[p]);
            int clo = tx + 32 * p, chi = clo + 16;
            o[clo] = vlo;
            o[chi] = vhi;
            if (writeY) { y[clo] = vlo * dr; y[chi] = vhi * dr; }
        }
    }
}

// ---------------- per-graph head --------------------------------------------
__global__ void __launch_bounds__(256) head_kernel(
        const float* __restrict__ Wc1, const float* __restrict__ bc1,
        const float* __restrict__ Wc2, const float* __restrict__ bc2,
        const float* __restrict__ g1,  const float* __restrict__ be1,
        const float* __restrict__ g2,  const float* __restrict__ be2,
        const float* __restrict__ Wl1, const float* __restrict__ bl1,
        const float* __restrict__ Wl2, const float* __restrict__ bl2,
        const float* __restrict__ rm1, const float* __restrict__ rv1,
        const float* __restrict__ rm2, const float* __restrict__ rv2,
        float* __restrict__ out) {
    __shared__ float keys[SMAX];
    __shared__ int   topk[KK];
    __shared__ float Wc1s[C1n * DD];
    __shared__ float c1s[C1n * KK];
    __shared__ float h2s[C2n * L2n];
    __shared__ float ps[FLAT];
    __shared__ float f1[128];
    __shared__ float red[256];

    int b = blockIdx.x, tid = threadIdx.x, bd = blockDim.x;
    int M = g_bcnt[b];
    if (M > SMAX) M = SMAX;
    int s = g_starts[b];

    for (int i = tid; i < C1n * DD; i += bd) Wc1s[i] = Wc1[i];
    for (int i = tid; i < M; i += bd) keys[i] = g_X[(size_t)(s + i) * DD + (DD - 1)];
    for (int i = tid; i < KK; i += bd) topk[i] = -1;
    __syncthreads();

    for (int i = tid; i < M; i += bd) {
        float ki = keys[i];
        int r = 0;
        for (int j = 0; j < M; ++j) {
            float kj = keys[j];
            r += (kj > ki) || (kj == ki && j < i);
        }
        if (r < KK) topk[r] = s + i;
    }
    __syncthreads();

    for (int o = tid; o < C1n * KK; o += bd) {
        int c = o & 15, k = o >> 4;
        int node = topk[k];
        float acc = __ldg(&bc1[c]);
        if (node >= 0) {
            const float* xr = g_X + (size_t)node * DD;
            const float* w = Wc1s + c * DD;
            #pragma unroll 4
            for (int d = 0; d < DD; ++d) acc += xr[d] * w[d];
        }
        float v = fmaxf(acc, 0.f);
        v = (v - __ldg(&rm1[c])) * (__ldg(&g1[c]) * rsqrtf(__ldg(&rv1[c]) + EPSc)) + __ldg(&be1[c]);
        c1s[c * KK + k] = v;
    }
    __syncthreads();

    for (int o = tid; o < C2n * L2n; o += bd) {
        int oc = o / L2n, tt = o % L2n;
        float acc = __ldg(&bc2[oc]);
        const float* w = Wc2 + oc * (C1n * KERNL);
        for (int ic = 0; ic < C1n; ++ic) {
            #pragma unroll
            for (int kk = 0; kk < KERNL; ++kk)
                acc += c1s[ic * KK + tt + kk] * __ldg(&w[ic * KERNL + kk]);
        }
        float v = fmaxf(acc, 0.f);
        v = (v - __ldg(&rm2[oc])) * (__ldg(&g2[oc]) * rsqrtf(__ldg(&rv2[oc]) + EPSc)) + __ldg(&be2[oc]);
        h2s[oc * L2n + tt] = v;
    }
    __syncthreads();

    for (int o = tid; o < FLAT; o += bd) {
        int oc = o / PL, l = o % PL;
        ps[o] = fmaxf(h2s[oc * L2n + 2 * l], h2s[oc * L2n + 2 * l + 1]);
    }
    __syncthreads();

    for (int j = tid; j < 128; j += bd) {
        float acc = __ldg(&bl1[j]);
        const float* w = Wl1 + j * FLAT;
        #pragma unroll 4
        for (int i = 0; i < FLAT; ++i) acc += ps[i] * __ldg(&w[i]);
        f1[j] = fmaxf(acc, 0.f);
    }
    __syncthreads();

    float p = 0.f;
    if (tid < 128) p = f1[tid] * __ldg(&Wl2[tid]);
    red[tid] = p;
    __syncthreads();
    for (int off = 128; off > 0; off >>= 1) {
        if (tid < off && tid + off < bd) red[tid] += red[tid + off];
        __syncthreads();
    }
    if (tid == 0) out[b] = red[0] + __ldg(&bl2[0]);
}

// ---------------- host orchestration ----------------------------------------
extern "C" void kernel_launch(void* const* d_in, const int* in_sizes, int n_in,
                              void* d_out, int out_size) {
    const int*   z     = (const int*)d_in[0];
    const int*   ei    = (const int*)d_in[1];
    const int*   batch = (const int*)d_in[2];
    const float* W0    = (const float*)d_in[3];
    const float* b0    = (const float*)d_in[4];
    const float* W1    = (const float*)d_in[5];
    const float* b1    = (const float*)d_in[6];
    const float* W2    = (const float*)d_in[7];
    const float* b2    = (const float*)d_in[8];
    const float* Wc1   = (const float*)d_in[9];
    const float* bc1   = (const float*)d_in[10];
    const float* Wc2   = (const float*)d_in[11];
    const float* bc2   = (const float*)d_in[12];
    const float* g1    = (const float*)d_in[13];
    const float* be1   = (const float*)d_in[14];
    const float* g2    = (const float*)d_in[15];
    const float* be2   = (const float*)d_in[16];
    const float* Wl1   = (const float*)d_in[17];
    const float* bl1   = (const float*)d_in[18];
    const float* Wl2   = (const float*)d_in[19];
    const float* bl2   = (const float*)d_in[20];
    const float* rm1   = (const float*)d_in[21];
    const float* rv1   = (const float*)d_in[22];
    const float* rm2   = (const float*)d_in[23];
    const float* rv2   = (const float*)d_in[24];
    float* out = (float*)d_out;

    const int* row = ei;
    const int* col = ei + Ee;

    init_kernel<<<(Nn + 255) / 256, 256>>>();                 // 0
    count_kernel<<<(Ee + 255) / 256, 256>>>(col, batch);      // 1
    scanA_kernel<<<SCANB, 256>>>();                           // 2
    scanB_kernel<<<1, SCANB>>>();                             // 3
    scanC_kernel<<<SCANB, 256>>>();                           // 4
    scan_batch_kernel<<<1, Bb>>>();                           // 5
    fill_kernel<<<(Ee + 255) / 256, 256>>>(row, col);         // 6

    agg0_kernel<<<Nn / 8, 256>>>(z);                          // 7
    gemm_tanh_kernel<<<Nn / 64, 128>>>(W0, b0, 0, 1);         // 8

    gather_kernel<<<Nn * 32 / 256, 256>>>();                  // 9
    gemm_tanh_kernel<<<Nn / 64, 128>>>(W1, b1, HID, 1);       // 10

    gather_kernel<<<Nn * 32 / 256, 256>>>();                  // 11
    gemm_tanh_kernel<<<Nn / 64, 128>>>(W2, b2, 2 * HID, 0);   // 12

    head_kernel<<<Bb, 256>>>(Wc1, bc1, Wc2, bc2, g1, be1, g2, be2,
                             Wl1, bl1, Wl2, bl2, rm1, rv1, rm2, rv2, out);  // 13
}